// round 10
// baseline (speedup 1.0000x reference)
#include <cuda_runtime.h>
#include <cstdint>

#define N_NODES 100000
#define FEAT 64
#define OUT_DIM 2

// Per-node projected message m = h @ W1  (L2-resident: 800 KB)
__device__ float2 g_m[N_NODES];

// ---------------------------------------------------------------------------
// Fused node kernel (296 blocks x 1024 thr, 2 blocks/SM):
//  1) warp-cooperative weight fold (32 warps x 4 pairs)
//  2) node phase: 8 lanes per node (warp = 4 nodes/iter), float4 loads
//     (2 LDG.128/lane/iter), 3-round multi-value shuffle reduce:
//       off=4 splits m* vs r*? -> routes m0/m1 and r0/r1 by q&4,
//       off=2 merges the two streams by q&2, off=1 finishes.
//     Lane q in {0,2,4,6} holds {m0,r0,m1,r1} fully reduced.
// ---------------------------------------------------------------------------
__global__ __launch_bounds__(1024, 2)
void node_kernel(const float* __restrict__ pos,
                 const float* __restrict__ vel,
                 const float* __restrict__ W_rel,
                 const float* __restrict__ b_rel,
                 const float* __restrict__ W_root,
                 const float* __restrict__ W_pred,
                 const float* __restrict__ b_pred,
                 float* __restrict__ out) {
    __shared__ float4 sW[FEAT];       // (W1[f][0], W1[f][1], W2[f][0], W2[f][1])
    __shared__ float  sbias[OUT_DIM];

    int t    = threadIdx.x;
    int warp = t >> 5;                // 0..31
    int lane = t & 31;

    // ---- fold: 32 warps x 4 (k,o)-pairs ----
    #pragma unroll
    for (int i = 0; i < 4; ++i) {
        int p = warp * 4 + i;
        int k = p >> 1;
        int o = p & 1;
        float wp0 = W_pred[lane * OUT_DIM + o];
        float wp1 = W_pred[(lane + 32) * OUT_DIM + o];
        float s1 = W_rel [k * FEAT + lane] * wp0 + W_rel [k * FEAT + lane + 32] * wp1;
        float s2 = W_root[k * FEAT + lane] * wp0 + W_root[k * FEAT + lane + 32] * wp1;
        #pragma unroll
        for (int off = 16; off > 0; off >>= 1) {
            s1 += __shfl_xor_sync(0xffffffffu, s1, off);
            s2 += __shfl_xor_sync(0xffffffffu, s2, off);
        }
        if (lane == 0) {
            float* w = (float*)&sW[k];
            w[o]     = s1;
            w[2 + o] = s2;
        }
    }
    if (warp < OUT_DIM) {
        int o = warp;
        float bb = b_rel[lane]      * W_pred[lane * OUT_DIM + o]
                 + b_rel[lane + 32] * W_pred[(lane + 32) * OUT_DIM + o];
        #pragma unroll
        for (int off = 16; off > 0; off >>= 1)
            bb += __shfl_xor_sync(0xffffffffu, bb, off);
        if (lane == 0) sbias[o] = bb + b_pred[o];
    }
    __syncthreads();

    // ---- node phase: 8 lanes per node ----
    int grp = lane >> 3;              // node within quad (0..3)
    int q   = lane & 7;               // float4 index within node (0..7)

    // per-lane weights for features q*4..q*4+3 (pos) and 32+q*4.. (vel)
    float4 wp[4], wv[4];
    #pragma unroll
    for (int e = 0; e < 4; ++e) {
        wp[e] = sW[q * 4 + e];
        wv[e] = sW[32 + q * 4 + e];
    }
    float bias0 = sbias[0], bias1 = sbias[1];
    int comp = q >> 2;                // output component 0/1
    float myb = comp ? bias1 : bias0;

    int wg    = blockIdx.x * 32 + warp;
    int total = gridDim.x * 32;       // 9472 warps

    for (int quad = wg; quad * 4 < N_NODES; quad += total) {
        int node = quad * 4 + grp;    // N_NODES % 4 == 0 -> always valid

        float4 p4 = __ldcs((const float4*)(pos + node * 32 + q * 4));
        float4 v4 = __ldcs((const float4*)(vel + node * 32 + q * 4));

        float m0 = 0.f, m1 = 0.f, r0 = 0.f, r1 = 0.f;
        #pragma unroll
        for (int e = 0; e < 4; ++e) {
            float pe = (&p4.x)[e];
            float ve = (&v4.x)[e];
            m0 += pe * wp[e].x + ve * wv[e].x;
            m1 += pe * wp[e].y + ve * wv[e].y;
            r0 += pe * wp[e].z + ve * wv[e].z;
            r1 += pe * wp[e].w + ve * wv[e].w;
        }

        // round 1 (off=4): q&4==0 lanes accumulate (m0,r0); q&4 lanes (m1,r1)
        float v1 = (q & 4) ? m1 : m0;
        float g1 = (q & 4) ? m0 : m1;
        v1 += __shfl_xor_sync(0xffffffffu, g1, 4);
        float v2 = (q & 4) ? r1 : r0;
        float g2 = (q & 4) ? r0 : r1;
        v2 += __shfl_xor_sync(0xffffffffu, g2, 4);
        // round 2 (off=2): select m-stream vs r-stream by q&2
        float vv = (q & 2) ? v2 : v1;
        float gg = (q & 2) ? v1 : v2;
        vv += __shfl_xor_sync(0xffffffffu, gg, 2);
        // round 3 (off=1): finish
        vv += __shfl_xor_sync(0xffffffffu, vv, 1);

        // lanes q=0: m0, q=4: m1, q=2: out0, q=6: out1
        if ((q & 1) == 0) {
            if ((q & 2) == 0) ((float*)&g_m[node])[comp] = vv;
            else              out[2 * node + comp] = vv + myb;
        }
    }
}

// ---------------------------------------------------------------------------
// Edge kernel (PDL secondary): load indices FIRST (independent of g_m),
// then cudaGridDependencySynchronize() to wait for node_kernel completion,
// then gather + vector RED. Proven R3/R9 shape: 8 edges/thread, single pass.
// ---------------------------------------------------------------------------
__device__ __forceinline__ void red_v2(float* addr, float2 v) {
    asm volatile("red.global.add.v2.f32 [%0], {%1, %2};"
                 :: "l"(addr), "f"(v.x), "f"(v.y) : "memory");
}

__global__ void edge_kernel(const int* __restrict__ src,
                            const int* __restrict__ dst,
                            float* __restrict__ out,
                            int n_edges) {
    int t = blockIdx.x * blockDim.x + threadIdx.x;
    int base = t * 8;
    bool full = (base + 7 < n_edges);

    int4 s0, s1, d0, d1;
    if (full) {
        s0 = __ldcs((const int4*)(src + base));
        s1 = __ldcs((const int4*)(src + base + 4));
        d0 = __ldcs((const int4*)(dst + base));
        d1 = __ldcs((const int4*)(dst + base + 4));
    }

    // Wait for node_kernel grid completion (PDL). Index loads above overlap
    // with the node kernel's tail.
    cudaGridDependencySynchronize();

    if (full) {
        float2 a0 = g_m[s0.x];
        float2 a1 = g_m[s0.y];
        float2 a2 = g_m[s0.z];
        float2 a3 = g_m[s0.w];
        float2 b0 = g_m[s1.x];
        float2 b1 = g_m[s1.y];
        float2 b2 = g_m[s1.z];
        float2 b3 = g_m[s1.w];
        red_v2(out + 2 * d0.x, a0);
        red_v2(out + 2 * d0.y, a1);
        red_v2(out + 2 * d0.z, a2);
        red_v2(out + 2 * d0.w, a3);
        red_v2(out + 2 * d1.x, b0);
        red_v2(out + 2 * d1.y, b1);
        red_v2(out + 2 * d1.z, b2);
        red_v2(out + 2 * d1.w, b3);
    } else {
        for (int i = base; i < n_edges; ++i) {
            float2 mm = g_m[src[i]];
            red_v2(out + 2 * dst[i], mm);
        }
    }
}

// ---------------------------------------------------------------------------
// Launch
// Inputs (metadata order): pos, vel, edge_index, W_rel, b_rel, W_root, W_pred, b_pred
// ---------------------------------------------------------------------------
extern "C" void kernel_launch(void* const* d_in, const int* in_sizes, int n_in,
                              void* d_out, int out_size) {
    const float* pos    = (const float*)d_in[0];
    const float* vel    = (const float*)d_in[1];
    const int*   eidx   = (const int*)  d_in[2];
    const float* W_rel  = (const float*)d_in[3];
    const float* b_rel  = (const float*)d_in[4];
    const float* W_root = (const float*)d_in[5];
    const float* W_pred = (const float*)d_in[6];
    const float* b_pred = (const float*)d_in[7];
    float* out = (float*)d_out;

    const int n_edges = in_sizes[2] / 2;          // 3.2M
    const int* src = eidx;
    const int* dst = eidx + n_edges;

    node_kernel<<<296, 1024>>>(pos, vel, W_rel, b_rel, W_root,
                               W_pred, b_pred, out);

    // PDL launch of the edge kernel
    int n_thr    = (n_edges + 7) / 8;
    int n_blocks = (n_thr + 255) / 256;

    cudaLaunchConfig_t cfg = {};
    cfg.gridDim  = dim3(n_blocks, 1, 1);
    cfg.blockDim = dim3(256, 1, 1);
    cudaLaunchAttribute attr[1];
    attr[0].id = cudaLaunchAttributeProgrammaticStreamSerialization;
    attr[0].val.programmaticStreamSerializationAllowed = 1;
    cfg.attrs    = attr;
    cfg.numAttrs = 1;
    cudaLaunchKernelEx(&cfg, edge_kernel, src, dst, out, n_edges);
}

// round 11
// speedup vs baseline: 1.2589x; 1.2589x over previous
#include <cuda_runtime.h>
#include <cuda_fp16.h>
#include <cstdint>

#define N_NODES 100000
#define FEAT 64
#define OUT_DIM 2

// Per-node projected message m = h @ W1, stored fp16x2 (400 KB -> ~57% L1 hit
// rate on random gathers vs 28% at fp32; REDs remain f32 so accumulation
// precision is unchanged, only the message value quantizes ~5e-4).
__device__ __half2 g_m[N_NODES];

// ---------------------------------------------------------------------------
// Fused node kernel (296 blocks x 1024 thr, 2 blocks/SM) — exact R9 structure:
//  1) warp-cooperative weight fold (32 warps x 4 pairs)
//  2) warp-per-node x4 unroll, multi-value butterfly (6 shuffles per node)
// ---------------------------------------------------------------------------
__global__ __launch_bounds__(1024, 2)
void node_kernel(const float* __restrict__ pos,
                 const float* __restrict__ vel,
                 const float* __restrict__ W_rel,
                 const float* __restrict__ b_rel,
                 const float* __restrict__ W_root,
                 const float* __restrict__ W_pred,
                 const float* __restrict__ b_pred,
                 float* __restrict__ out) {
    __shared__ float4 sW[FEAT];       // (W1[f][0], W1[f][1], W2[f][0], W2[f][1])
    __shared__ float  sbias[OUT_DIM];

    int t    = threadIdx.x;
    int warp = t >> 5;                // 0..31
    int lane = t & 31;

    // ---- fold: 32 warps x 4 (k,o)-pairs ----
    #pragma unroll
    for (int i = 0; i < 4; ++i) {
        int p = warp * 4 + i;
        int k = p >> 1;
        int o = p & 1;
        float wp0 = W_pred[lane * OUT_DIM + o];
        float wp1 = W_pred[(lane + 32) * OUT_DIM + o];
        float s1 = W_rel [k * FEAT + lane] * wp0 + W_rel [k * FEAT + lane + 32] * wp1;
        float s2 = W_root[k * FEAT + lane] * wp0 + W_root[k * FEAT + lane + 32] * wp1;
        #pragma unroll
        for (int off = 16; off > 0; off >>= 1) {
            s1 += __shfl_xor_sync(0xffffffffu, s1, off);
            s2 += __shfl_xor_sync(0xffffffffu, s2, off);
        }
        if (lane == 0) {
            float* w = (float*)&sW[k];
            w[o]     = s1;
            w[2 + o] = s2;
        }
    }
    if (warp < OUT_DIM) {
        int o = warp;
        float bb = b_rel[lane]      * W_pred[lane * OUT_DIM + o]
                 + b_rel[lane + 32] * W_pred[(lane + 32) * OUT_DIM + o];
        #pragma unroll
        for (int off = 16; off > 0; off >>= 1)
            bb += __shfl_xor_sync(0xffffffffu, bb, off);
        if (lane == 0) sbias[o] = bb + b_pred[o];
    }
    __syncthreads();

    float4 wpk = sW[lane];            // weights for pos feature `lane`
    float4 wvk = sW[32 + lane];       // weights for vel feature `lane+32`
    float bias0 = sbias[0], bias1 = sbias[1];

    bool laneSel = (lane & 7) == 0;   // lanes 0,8,16,24 write results
    bool isM     = (lane & 8) == 0;   // 0,16 -> g_m ; 8,24 -> out
    int  hi      = lane >> 4;         // component 0 or 1

    __half* gm_h = (__half*)g_m;      // scalar half view for per-lane stores

    int wg    = blockIdx.x * 32 + warp;
    int total = gridDim.x * 32;       // 9472 warps

    for (int n0 = wg * 4; n0 < N_NODES; n0 += total * 4) {
        float P[4], V[4];
        #pragma unroll
        for (int j = 0; j < 4; ++j) P[j] = __ldcs(pos + (n0 + j) * 32 + lane);
        #pragma unroll
        for (int j = 0; j < 4; ++j) V[j] = __ldcs(vel + (n0 + j) * 32 + lane);

        float y[4];
        #pragma unroll
        for (int j = 0; j < 4; ++j) {
            float m0 = P[j] * wpk.x + V[j] * wvk.x;
            float m1 = P[j] * wpk.y + V[j] * wvk.y;
            float r0 = P[j] * wpk.z + V[j] * wvk.z;
            float r1 = P[j] * wpk.w + V[j] * wvk.w;

            // round 1 (off=16): halves -> m0|m1 and r0|r1
            float xA = (lane & 16) ? m1 : m0;
            float gA = (lane & 16) ? m0 : m1;
            xA += __shfl_xor_sync(0xffffffffu, gA, 16);
            float xB = (lane & 16) ? r1 : r0;
            float gB = (lane & 16) ? r0 : r1;
            xB += __shfl_xor_sync(0xffffffffu, gB, 16);
            // round 2 (off=8): quarters -> [m|r|m|r]
            float yy = (lane & 8) ? xB : xA;
            float gg = (lane & 8) ? xA : xB;
            yy += __shfl_xor_sync(0xffffffffu, gg, 8);
            // rounds 3-5: finish within 8-lane groups
            yy += __shfl_xor_sync(0xffffffffu, yy, 4);
            yy += __shfl_xor_sync(0xffffffffu, yy, 2);
            yy += __shfl_xor_sync(0xffffffffu, yy, 1);
            y[j] = yy;
        }

        if (laneSel) {
            #pragma unroll
            for (int j = 0; j < 4; ++j) {
                int n = n0 + j;
                if (isM) gm_h[2 * n + hi] = __float2half(y[j]);
                else     out[2 * n + hi] = y[j] + (hi ? bias1 : bias0);
            }
        }
    }
}

// ---------------------------------------------------------------------------
// Edge kernel: EXACT R9 shape (proven 30.6us): 8 edges/thread, single pass,
// 1563 blocks x 256. Gather fp16x2 (L1-friendlier), convert, RED in f32.
// ---------------------------------------------------------------------------
__device__ __forceinline__ void red_v2(float* addr, float2 v) {
    asm volatile("red.global.add.v2.f32 [%0], {%1, %2};"
                 :: "l"(addr), "f"(v.x), "f"(v.y) : "memory");
}

__global__ void edge_kernel(const int* __restrict__ src,
                            const int* __restrict__ dst,
                            float* __restrict__ out,
                            int n_edges) {
    int t = blockIdx.x * blockDim.x + threadIdx.x;
    int base = t * 8;
    if (base + 7 < n_edges) {
        int4 s0 = __ldcs((const int4*)(src + base));
        int4 s1 = __ldcs((const int4*)(src + base + 4));
        int4 d0 = __ldcs((const int4*)(dst + base));
        int4 d1 = __ldcs((const int4*)(dst + base + 4));
        float2 a0 = __half22float2(g_m[s0.x]);
        float2 a1 = __half22float2(g_m[s0.y]);
        float2 a2 = __half22float2(g_m[s0.z]);
        float2 a3 = __half22float2(g_m[s0.w]);
        float2 b0 = __half22float2(g_m[s1.x]);
        float2 b1 = __half22float2(g_m[s1.y]);
        float2 b2 = __half22float2(g_m[s1.z]);
        float2 b3 = __half22float2(g_m[s1.w]);
        red_v2(out + 2 * d0.x, a0);
        red_v2(out + 2 * d0.y, a1);
        red_v2(out + 2 * d0.z, a2);
        red_v2(out + 2 * d0.w, a3);
        red_v2(out + 2 * d1.x, b0);
        red_v2(out + 2 * d1.y, b1);
        red_v2(out + 2 * d1.z, b2);
        red_v2(out + 2 * d1.w, b3);
    } else {
        for (int i = base; i < n_edges; ++i) {
            float2 mm = __half22float2(g_m[src[i]]);
            red_v2(out + 2 * dst[i], mm);
        }
    }
}

// ---------------------------------------------------------------------------
// Launch
// Inputs (metadata order): pos, vel, edge_index, W_rel, b_rel, W_root, W_pred, b_pred
// ---------------------------------------------------------------------------
extern "C" void kernel_launch(void* const* d_in, const int* in_sizes, int n_in,
                              void* d_out, int out_size) {
    const float* pos    = (const float*)d_in[0];
    const float* vel    = (const float*)d_in[1];
    const int*   eidx   = (const int*)  d_in[2];
    const float* W_rel  = (const float*)d_in[3];
    const float* b_rel  = (const float*)d_in[4];
    const float* W_root = (const float*)d_in[5];
    const float* W_pred = (const float*)d_in[6];
    const float* b_pred = (const float*)d_in[7];
    float* out = (float*)d_out;

    const int n_edges = in_sizes[2] / 2;          // 3.2M
    const int* src = eidx;
    const int* dst = eidx + n_edges;

    node_kernel<<<296, 1024>>>(pos, vel, W_rel, b_rel, W_root,
                               W_pred, b_pred, out);

    int n_thr = (n_edges + 7) / 8;
    edge_kernel<<<(n_thr + 255) / 256, 256>>>(src, dst, out, n_edges);
}

// round 12
// speedup vs baseline: 1.2600x; 1.0008x over previous
#include <cuda_runtime.h>
#include <cuda_fp16.h>
#include <cstdint>

#define N_NODES 100000
#define FEAT 64
#define OUT_DIM 2

// Per-node projected message m = h @ W1, stored fp16x2 (400 KB, L2/L1 resident)
__device__ __half2 g_m[N_NODES];

// ---------------------------------------------------------------------------
// Fused node kernel (296 blocks x 1024 thr, 2 blocks/SM) — exact R11:
//  1) warp-cooperative weight fold (32 warps x 4 pairs)
//  2) warp-per-node x4 unroll, multi-value butterfly (6 shuffles per node)
// ---------------------------------------------------------------------------
__global__ __launch_bounds__(1024, 2)
void node_kernel(const float* __restrict__ pos,
                 const float* __restrict__ vel,
                 const float* __restrict__ W_rel,
                 const float* __restrict__ b_rel,
                 const float* __restrict__ W_root,
                 const float* __restrict__ W_pred,
                 const float* __restrict__ b_pred,
                 float* __restrict__ out) {
    __shared__ float4 sW[FEAT];       // (W1[f][0], W1[f][1], W2[f][0], W2[f][1])
    __shared__ float  sbias[OUT_DIM];

    int t    = threadIdx.x;
    int warp = t >> 5;                // 0..31
    int lane = t & 31;

    // ---- fold: 32 warps x 4 (k,o)-pairs ----
    #pragma unroll
    for (int i = 0; i < 4; ++i) {
        int p = warp * 4 + i;
        int k = p >> 1;
        int o = p & 1;
        float wp0 = W_pred[lane * OUT_DIM + o];
        float wp1 = W_pred[(lane + 32) * OUT_DIM + o];
        float s1 = W_rel [k * FEAT + lane] * wp0 + W_rel [k * FEAT + lane + 32] * wp1;
        float s2 = W_root[k * FEAT + lane] * wp0 + W_root[k * FEAT + lane + 32] * wp1;
        #pragma unroll
        for (int off = 16; off > 0; off >>= 1) {
            s1 += __shfl_xor_sync(0xffffffffu, s1, off);
            s2 += __shfl_xor_sync(0xffffffffu, s2, off);
        }
        if (lane == 0) {
            float* w = (float*)&sW[k];
            w[o]     = s1;
            w[2 + o] = s2;
        }
    }
    if (warp < OUT_DIM) {
        int o = warp;
        float bb = b_rel[lane]      * W_pred[lane * OUT_DIM + o]
                 + b_rel[lane + 32] * W_pred[(lane + 32) * OUT_DIM + o];
        #pragma unroll
        for (int off = 16; off > 0; off >>= 1)
            bb += __shfl_xor_sync(0xffffffffu, bb, off);
        if (lane == 0) sbias[o] = bb + b_pred[o];
    }
    __syncthreads();

    float4 wpk = sW[lane];            // weights for pos feature `lane`
    float4 wvk = sW[32 + lane];       // weights for vel feature `lane+32`
    float bias0 = sbias[0], bias1 = sbias[1];

    bool laneSel = (lane & 7) == 0;   // lanes 0,8,16,24 write results
    bool isM     = (lane & 8) == 0;   // 0,16 -> g_m ; 8,24 -> out
    int  hi      = lane >> 4;         // component 0 or 1

    __half* gm_h = (__half*)g_m;      // scalar half view for per-lane stores

    int wg    = blockIdx.x * 32 + warp;
    int total = gridDim.x * 32;       // 9472 warps

    for (int n0 = wg * 4; n0 < N_NODES; n0 += total * 4) {
        float P[4], V[4];
        #pragma unroll
        for (int j = 0; j < 4; ++j) P[j] = __ldcs(pos + (n0 + j) * 32 + lane);
        #pragma unroll
        for (int j = 0; j < 4; ++j) V[j] = __ldcs(vel + (n0 + j) * 32 + lane);

        float y[4];
        #pragma unroll
        for (int j = 0; j < 4; ++j) {
            float m0 = P[j] * wpk.x + V[j] * wvk.x;
            float m1 = P[j] * wpk.y + V[j] * wvk.y;
            float r0 = P[j] * wpk.z + V[j] * wvk.z;
            float r1 = P[j] * wpk.w + V[j] * wvk.w;

            float xA = (lane & 16) ? m1 : m0;
            float gA = (lane & 16) ? m0 : m1;
            xA += __shfl_xor_sync(0xffffffffu, gA, 16);
            float xB = (lane & 16) ? r1 : r0;
            float gB = (lane & 16) ? r0 : r1;
            xB += __shfl_xor_sync(0xffffffffu, gB, 16);
            float yy = (lane & 8) ? xB : xA;
            float gg = (lane & 8) ? xA : xB;
            yy += __shfl_xor_sync(0xffffffffu, gg, 8);
            yy += __shfl_xor_sync(0xffffffffu, yy, 4);
            yy += __shfl_xor_sync(0xffffffffu, yy, 2);
            yy += __shfl_xor_sync(0xffffffffu, yy, 1);
            y[j] = yy;
        }

        if (laneSel) {
            #pragma unroll
            for (int j = 0; j < 4; ++j) {
                int n = n0 + j;
                if (isM) gm_h[2 * n + hi] = __float2half(y[j]);
                else     out[2 * n + hi] = y[j] + (hi ? bias1 : bias0);
            }
        }
    }
}

// ---------------------------------------------------------------------------
// Edge kernel (PDL secondary, sync-at-top): cudaGridDependencySynchronize()
// is the FIRST statement — no state held across the wait, so register count
// stays at the proven 32 (R10 held indices across the sync -> 44 regs, slow).
// Blocks spawn + run prologue while node_kernel drains.
// 8 edges/thread, single pass, 1563 blocks x 256 (proven optimum).
// ---------------------------------------------------------------------------
__device__ __forceinline__ void red_v2(float* addr, float2 v) {
    asm volatile("red.global.add.v2.f32 [%0], {%1, %2};"
                 :: "l"(addr), "f"(v.x), "f"(v.y) : "memory");
}

__global__ void edge_kernel(const int* __restrict__ src,
                            const int* __restrict__ dst,
                            float* __restrict__ out,
                            int n_edges) {
    cudaGridDependencySynchronize();

    int t = blockIdx.x * blockDim.x + threadIdx.x;
    int base = t * 8;
    if (base + 7 < n_edges) {
        int4 s0 = __ldcs((const int4*)(src + base));
        int4 s1 = __ldcs((const int4*)(src + base + 4));
        int4 d0 = __ldcs((const int4*)(dst + base));
        int4 d1 = __ldcs((const int4*)(dst + base + 4));
        float2 a0 = __half22float2(g_m[s0.x]);
        float2 a1 = __half22float2(g_m[s0.y]);
        float2 a2 = __half22float2(g_m[s0.z]);
        float2 a3 = __half22float2(g_m[s0.w]);
        float2 b0 = __half22float2(g_m[s1.x]);
        float2 b1 = __half22float2(g_m[s1.y]);
        float2 b2 = __half22float2(g_m[s1.z]);
        float2 b3 = __half22float2(g_m[s1.w]);
        red_v2(out + 2 * d0.x, a0);
        red_v2(out + 2 * d0.y, a1);
        red_v2(out + 2 * d0.z, a2);
        red_v2(out + 2 * d0.w, a3);
        red_v2(out + 2 * d1.x, b0);
        red_v2(out + 2 * d1.y, b1);
        red_v2(out + 2 * d1.z, b2);
        red_v2(out + 2 * d1.w, b3);
    } else {
        for (int i = base; i < n_edges; ++i) {
            float2 mm = __half22float2(g_m[src[i]]);
            red_v2(out + 2 * dst[i], mm);
        }
    }
}

// ---------------------------------------------------------------------------
// Launch
// Inputs (metadata order): pos, vel, edge_index, W_rel, b_rel, W_root, W_pred, b_pred
// ---------------------------------------------------------------------------
extern "C" void kernel_launch(void* const* d_in, const int* in_sizes, int n_in,
                              void* d_out, int out_size) {
    const float* pos    = (const float*)d_in[0];
    const float* vel    = (const float*)d_in[1];
    const int*   eidx   = (const int*)  d_in[2];
    const float* W_rel  = (const float*)d_in[3];
    const float* b_rel  = (const float*)d_in[4];
    const float* W_root = (const float*)d_in[5];
    const float* W_pred = (const float*)d_in[6];
    const float* b_pred = (const float*)d_in[7];
    float* out = (float*)d_out;

    const int n_edges = in_sizes[2] / 2;          // 3.2M
    const int* src = eidx;
    const int* dst = eidx + n_edges;

    node_kernel<<<296, 1024>>>(pos, vel, W_rel, b_rel, W_root,
                               W_pred, b_pred, out);

    // PDL launch: edge blocks spawn while node_kernel finishes; the in-kernel
    // cudaGridDependencySynchronize() provides the ordering.
    int n_thr    = (n_edges + 7) / 8;
    int n_blocks = (n_thr + 255) / 256;

    cudaLaunchConfig_t cfg = {};
    cfg.gridDim  = dim3(n_blocks, 1, 1);
    cfg.blockDim = dim3(256, 1, 1);
    cudaLaunchAttribute attr[1];
    attr[0].id = cudaLaunchAttributeProgrammaticStreamSerialization;
    attr[0].val.programmaticStreamSerializationAllowed = 1;
    cfg.attrs    = attr;
    cfg.numAttrs = 1;
    cudaLaunchKernelEx(&cfg, edge_kernel, src, dst, out, n_edges);
}